// round 1
// baseline (speedup 1.0000x reference)
#include <cuda_runtime.h>

#define B 16
#define CIN 16
#define DD 16
#define HH 128
#define WW 128
#define COUT 64
#define HW (HH*WW)

// ---- device scratch (no allocs allowed) ----
__device__ float g_s[B*CIN*HW];        // depth-summed x: [b][c][h][w]  (16.8 MB)
__device__ float g_w[48*9*COUT];       // transposed weights [ci48][k9][co64], sign folded

// ---- f32x2 helpers (Blackwell packed fp32 pipe: 2x FFMA throughput) ----
__device__ __forceinline__ unsigned long long pk2(float lo, float hi) {
    unsigned long long r;
    asm("mov.b64 %0, {%1, %2};" : "=l"(r) : "f"(lo), "f"(hi));
    return r;
}
__device__ __forceinline__ void fma2(unsigned long long& d, unsigned long long a, unsigned long long b) {
    asm("fma.rn.f32x2 %0, %1, %2, %0;" : "+l"(d) : "l"(a), "l"(b));
}
__device__ __forceinline__ void unp2(unsigned long long v, float& a, float& b) {
    asm("mov.b64 {%0, %1}, %2;" : "=f"(a), "=f"(b) : "l"(v));
}

// ============================================================
// Kernel 0: transpose weights to [ci48][kh][kw][co64], fold signs
//   ci 0-15  <- wsum   (+)
//   ci 16-31 <- wfront (-)
//   ci 32-47 <- wback  (-)
// ============================================================
__global__ void prep_w(const float* __restrict__ wsum,
                       const float* __restrict__ wfront,
                       const float* __restrict__ wback) {
    int idx = blockIdx.x * blockDim.x + threadIdx.x;
    if (idx >= 48*9*COUT) return;
    int co = idx & 63;
    int k  = (idx >> 6) % 9;
    int ci = idx / (9*64);
    int grp = ci >> 4;
    int c   = ci & 15;
    const float* src = (grp == 0) ? wsum : (grp == 1 ? wfront : wback);
    float v = src[(co*CIN + c)*9 + k];
    if (grp) v = -v;
    g_w[(ci*9 + k)*COUT + co] = v;
}

// ============================================================
// Kernel 1: depth sum  g_s[b,c,h,w] = sum_z x[b,c,z,h,w]
// vectorized float4, DRAM-bound (268 MB read, 17 MB write)
// ============================================================
__global__ void depth_sum(const float* __restrict__ x) {
    int i = blockIdx.x * blockDim.x + threadIdx.x;   // over B*CIN*HW/4
    if (i >= B*CIN*(HW/4)) return;
    int bc = i / (HW/4);
    int r  = i - bc*(HW/4);
    const float4* p = reinterpret_cast<const float4*>(x) + (size_t)bc*DD*(HW/4) + r;
    float4 acc = p[0];
    #pragma unroll
    for (int z = 1; z < DD; z++) {
        float4 v = p[(size_t)z*(HW/4)];
        acc.x += v.x; acc.y += v.y; acc.z += v.z; acc.w += v.w;
    }
    reinterpret_cast<float4*>(g_s)[(size_t)bc*(HW/4) + r] = acc;
}

// ============================================================
// Kernel 2: fused 3x3 conv (48->64) + bias + channel softmax + tanh
//
// Block = 8x32 pixel tile, 256 threads.
// Thread (cog = tid>>5 in 0..7, pg = tid&31):
//   owns couts [cog*8, cog*8+8) x 8 pixels (row pg>>2, cols (pg&3)*8 ..+8)
//   32 f32x2 accumulators (pixel pairs).
// smem: weights 48*9*64 (108 KB) + bias + union{ patch 48*10*35, logits 256*65 }
// Patch pitch 35 -> lane addr (35r + 8c) mod 32 is a permutation: conflict-free.
// ============================================================
#define T_H 8
#define T_W 32
#define P_ROWS 10
#define P_PITCH 35
#define P_CI_STRIDE (P_ROWS*P_PITCH)          // 350
#define SMEM_W_FLOATS (48*9*64)               // 27648
#define UNION_OFF (SMEM_W_FLOATS + 64)        // + bias
#define UNION_FLOATS (48*P_CI_STRIDE)         // 16800 (> 256*65 = 16640)
#define SMEM_FLOATS (UNION_OFF + UNION_FLOATS)
#define SMEM_BYTES (SMEM_FLOATS*4)            // 178048 B

__global__ void __launch_bounds__(256, 1)
conv_softmax(const float* __restrict__ x,
             const float* __restrict__ bias,
             float* __restrict__ out) {
    extern __shared__ float sm[];
    float* sw    = sm;
    float* sb    = sm + SMEM_W_FLOATS;
    float* patch = sm + UNION_OFF;

    const int tid  = threadIdx.x;
    const int b    = blockIdx.y;
    const int tile = blockIdx.x;              // 0..63
    const int th0  = (tile >> 2) * T_H;       // 16 row tiles
    const int tw0  = (tile & 3) * T_W;        // 4 col tiles

    // load weights + bias into smem
    for (int i = tid; i < SMEM_W_FLOATS; i += 256) sw[i] = g_w[i];
    if (tid < 64) sb[tid] = bias[tid];

    // load input patch [48][10][35], zero-padded at image borders
    for (int i = tid; i < 48*P_ROWS*34; i += 256) {
        int ci  = i / (P_ROWS*34);
        int rem = i - ci*(P_ROWS*34);
        int r = rem / 34, c = rem - (rem/34)*34;
        int gh = th0 + r - 1, gw = tw0 + c - 1;
        float v = 0.0f;
        if ((unsigned)gh < HH && (unsigned)gw < WW) {
            int grp = ci >> 4, ch = ci & 15;
            const float* src;
            if (grp == 0) src = g_s + (size_t)(b*CIN + ch)*HW;
            else          src = x + ((size_t)(b*CIN + ch)*DD + (grp == 1 ? 0 : DD-1))*HW;
            v = src[gh*WW + gw];
        }
        patch[ci*P_CI_STRIDE + r*P_PITCH + c] = v;
    }
    __syncthreads();

    const int cog  = tid >> 5;
    const int pg   = tid & 31;
    const int prow = pg >> 2;
    const int pcol = (pg & 3) << 3;

    unsigned long long acc[8][4];
    #pragma unroll
    for (int c = 0; c < 8; c++)
        #pragma unroll
        for (int j = 0; j < 4; j++) acc[c][j] = 0ULL;

    const float* wb = sw + (cog << 3);

    for (int ci = 0; ci < 48; ci++) {
        const float* pb = patch + ci*P_CI_STRIDE + prow*P_PITCH + pcol;
        #pragma unroll
        for (int kh = 0; kh < 3; kh++) {
            const float* ib = pb + kh*P_PITCH;
            float in[10];
            #pragma unroll
            for (int t = 0; t < 10; t++) in[t] = ib[t];
            const float* wrow = wb + (ci*9 + kh*3)*64;
            #pragma unroll
            for (int kw = 0; kw < 3; kw++) {
                float4 wv0 = *reinterpret_cast<const float4*>(wrow + kw*64);
                float4 wv1 = *reinterpret_cast<const float4*>(wrow + kw*64 + 4);
                unsigned long long in2[4];
                #pragma unroll
                for (int j = 0; j < 4; j++)
                    in2[j] = pk2(in[2*j + kw], in[2*j + 1 + kw]);
                float wf[8] = {wv0.x, wv0.y, wv0.z, wv0.w, wv1.x, wv1.y, wv1.z, wv1.w};
                #pragma unroll
                for (int c = 0; c < 8; c++) {
                    unsigned long long w2 = pk2(wf[c], wf[c]);
                    #pragma unroll
                    for (int j = 0; j < 4; j++) fma2(acc[c][j], in2[j], w2);
                }
            }
        }
    }
    __syncthreads();   // patch no longer needed; reuse as logits

    // scatter logits into [pixel][co] with pitch 65 (conflict-free reads)
    float* lg = patch;
    #pragma unroll
    for (int c = 0; c < 8; c++) {
        int co = (cog << 3) + c;
        #pragma unroll
        for (int j = 0; j < 4; j++) {
            float a, v;
            unp2(acc[c][j], a, v);
            int px = (pg << 3) + 2*j;          // linear pixel = row*32 + col
            lg[px*65 + co]     = a;
            lg[(px+1)*65 + co] = v;
        }
    }
    __syncthreads();

    // epilogue: thread = one pixel (tid), softmax over 64 channels + tanh
    float* myl = lg + tid*65;
    float mx = -3.4e38f;
    #pragma unroll
    for (int co = 0; co < 64; co++) {
        float v = myl[co] + sb[co];
        myl[co] = v;
        mx = fmaxf(mx, v);
    }
    float s = 0.0f;
    #pragma unroll
    for (int co = 0; co < 64; co++) {
        float e = __expf(myl[co] - mx);
        myl[co] = e;
        s += e;
    }
    float inv = 1.0f / s;
    int gh = th0 + (tid >> 5);
    int gw = tw0 + (tid & 31);
    float* ob = out + (size_t)b*COUT*HW + gh*WW + gw;
    #pragma unroll
    for (int co = 0; co < 64; co++)
        ob[(size_t)co*HW] = tanhf(myl[co]*inv);
}

// ============================================================
extern "C" void kernel_launch(void* const* d_in, const int* in_sizes, int n_in,
                              void* d_out, int out_size) {
    const float* x      = (const float*)d_in[0];
    const float* wsum   = (const float*)d_in[1];
    const float* wfront = (const float*)d_in[2];
    const float* wback  = (const float*)d_in[3];
    const float* bias   = (const float*)d_in[4];
    float* out = (float*)d_out;

    cudaFuncSetAttribute(conv_softmax, cudaFuncAttributeMaxDynamicSharedMemorySize, SMEM_BYTES);

    prep_w<<<(48*9*COUT + 255)/256, 256>>>(wsum, wfront, wback);
    depth_sum<<<(B*CIN*(HW/4) + 255)/256, 256>>>(x);
    dim3 grid(64, B);
    conv_softmax<<<grid, 256, SMEM_BYTES>>>(x, bias, out);
}